// round 1
// baseline (speedup 1.0000x reference)
#include <cuda_runtime.h>

#define LBL 256

// Confusion matrix scratch (no cudaMalloc allowed) — zeroed every launch.
__device__ int d_C[LBL * LBL];

__global__ void zero_kernel() {
    d_C[blockIdx.x * blockDim.x + threadIdx.x] = 0;
}

__global__ void hist_kernel(const int4* __restrict__ p4,
                            const int4* __restrict__ g4,
                            const int*  __restrict__ p_s,
                            const int*  __restrict__ g_s,
                            int n4, int n) {
    int i = blockIdx.x * blockDim.x + threadIdx.x;
    int stride = gridDim.x * blockDim.x;
    for (; i < n4; i += stride) {
        int4 p = __ldg(&p4[i]);
        int4 g = __ldg(&g4[i]);
        atomicAdd(&d_C[(g.x << 8) | p.x], 1);
        atomicAdd(&d_C[(g.y << 8) | p.y], 1);
        atomicAdd(&d_C[(g.z << 8) | p.z], 1);
        atomicAdd(&d_C[(g.w << 8) | p.w], 1);
    }
    // tail (n not divisible by 4) — handled by block 0 only
    if (blockIdx.x == 0) {
        int base = n4 * 4;
        int rem = n - base;
        if ((int)threadIdx.x < rem) {
            int p = __ldg(&p_s[base + threadIdx.x]);
            int g = __ldg(&g_s[base + threadIdx.x]);
            atomicAdd(&d_C[(g << 8) | p], 1);
        }
    }
}

__global__ void finalize_kernel(float* __restrict__ out) {
    __shared__ int   gt_size[LBL], pred_size[LBL];
    __shared__ int   best_p[LBL], inter_s[LBL], rowpairs_s[LBL], colcnt_s[LBL];
    __shared__ unsigned char has_s[LBL];
    int t = threadIdx.x;

    // Full row/col sums (background included, matching reference gt_size/pred_size)
    int rs = 0, cs = 0;
    #pragma unroll 8
    for (int j = 0; j < LBL; j++) {
        rs += d_C[t * LBL + j];
        cs += d_C[j * LBL + t];
    }
    gt_size[t]  = rs;
    pred_size[t] = cs;
    __syncthreads();

    // Per-row (gt label t>0), over Cnz (row 0 / col 0 zeroed => loop from 1):
    //   rowpairs: #overlapping preds; M: first p with 2*C > gt_size (argmax of bool);
    // Per-col (pred label t>0): count of gt rows overlapping (for ea).
    int rowpairs = 0, bp = 0, iv = 0, colcnt = 0;
    bool hv = false;
    if (t > 0) {
        int gs = gt_size[t];
        for (int p = 1; p < LBL; p++) {
            int c = d_C[t * LBL + p];
            rowpairs += (c > 0);
            if (!hv && 2 * c > gs) { hv = true; bp = p; iv = c; }
            colcnt += (d_C[p * LBL + t] > 0);
        }
    }
    rowpairs_s[t] = rowpairs;
    best_p[t]     = bp;
    inter_s[t]    = iv;
    has_s[t]      = hv ? 1 : 0;
    colcnt_s[t]   = colcnt;
    __syncthreads();

    if (t == 0) {
        int pairs = 0, ea = 0, num_gt = 0, num_pred = 0;
        for (int i = 1; i < LBL; i++) {
            pairs   += rowpairs_s[i];
            ea      += (colcnt_s[i] > 1);
            num_gt  += (gt_size[i]  > 0);
            num_pred+= (pred_size[i] > 0);
        }
        bool used[LBL];
        for (int i = 0; i < LBL; i++) used[i] = false;
        int tp = 0;
        float seg_sum = 0.0f;
        // Greedy scan in ascending gt-label order (matches jax.lax.scan order)
        for (int g = 1; g < LBL; g++) {
            int pl = best_p[g];
            if (has_s[g] && !used[pl]) {
                int uni = gt_size[g] + pred_size[pl] - inter_s[g];
                if (uni < 1) uni = 1;
                seg_sum += (float)inter_s[g] / (float)uni;
                used[pl] = true;
                tp++;
            }
        }
        float ng = (float)(num_gt > 0 ? num_gt : 1);
        float seg = seg_sum / ng;
        int ns = pairs - tp;
        int fn = num_gt - tp;
        int fp = num_pred - tp;
        float det = 1.0f - (float)(fp + fn + ns + ea) / ng;
        bool both_empty = (num_gt == 0) && (num_pred == 0);
        bool any_empty  = (num_gt == 0) || (num_pred == 0);
        if (both_empty)     { seg = 1.0f; det = 1.0f; }
        else if (any_empty) { seg = 0.0f; det = 0.0f; }
        out[0] = seg;
        out[1] = det;
    }
}

extern "C" void kernel_launch(void* const* d_in, const int* in_sizes, int n_in,
                              void* d_out, int out_size) {
    const int* pred = (const int*)d_in[0];
    const int* gt   = (const int*)d_in[1];
    int n  = in_sizes[0];
    int n4 = n / 4;

    zero_kernel<<<LBL, LBL>>>();
    hist_kernel<<<2048, 256>>>((const int4*)pred, (const int4*)gt, pred, gt, n4, n);
    finalize_kernel<<<1, LBL>>>((float*)d_out);
}

// round 2
// speedup vs baseline: 1.4455x; 1.4455x over previous
#include <cuda_runtime.h>

#define LBL    256
#define NBINS  (LBL * LBL)     // 65536
#define NWORDS (NBINS / 2)     // 32768 u32 words, 2 packed u16 bins each
#define NB     296             // 2 waves of 148; guarantees <65536 pixels/block
#define THREADS 1024
#define SMEM_BYTES (NWORDS * 4)  // 131072

__device__ int          d_C[NBINS];
__device__ unsigned int d_partial[NB * NWORDS];   // per-block u16-packed partials

__global__ void hist_kernel(const int4* __restrict__ p4,
                            const int4* __restrict__ g4,
                            const int*  __restrict__ p_s,
                            const int*  __restrict__ g_s,
                            int n4, int n) {
    extern __shared__ unsigned int sh[];   // 32768 words = 65536 u16 bins
    for (int w = threadIdx.x; w < NWORDS; w += THREADS) sh[w] = 0u;
    __syncthreads();

    int i = blockIdx.x * THREADS + threadIdx.x;
    int stride = gridDim.x * THREADS;
    for (; i < n4; i += stride) {
        int4 p = __ldg(&p4[i]);
        int4 g = __ldg(&g4[i]);
        int b;
        b = (g.x << 8) | p.x; atomicAdd(&sh[b >> 1], 1u << ((b & 1) << 4));
        b = (g.y << 8) | p.y; atomicAdd(&sh[b >> 1], 1u << ((b & 1) << 4));
        b = (g.z << 8) | p.z; atomicAdd(&sh[b >> 1], 1u << ((b & 1) << 4));
        b = (g.w << 8) | p.w; atomicAdd(&sh[b >> 1], 1u << ((b & 1) << 4));
    }
    // tail (n % 4) handled by block 0, folded into its smem histogram
    if (blockIdx.x == 0) {
        int base = n4 * 4;
        int rem = n - base;
        if ((int)threadIdx.x < rem) {
            int p = __ldg(&p_s[base + threadIdx.x]);
            int g = __ldg(&g_s[base + threadIdx.x]);
            int b = (g << 8) | p;
            atomicAdd(&sh[b >> 1], 1u << ((b & 1) << 4));
        }
    }
    __syncthreads();

    // Non-atomic flush: full 128KB partial, coalesced STG
    unsigned int* out = d_partial + (size_t)blockIdx.x * NWORDS;
    for (int w = threadIdx.x; w < NWORDS; w += THREADS) out[w] = sh[w];
}

// Sum 296 u16-packed partials into d_C. One thread per packed word.
__global__ void reduce_kernel() {
    int w = blockIdx.x * blockDim.x + threadIdx.x;   // 0..NWORDS-1
    if (w >= NWORDS) return;
    unsigned int lo = 0, hi = 0;
    #pragma unroll 8
    for (int b = 0; b < NB; b++) {
        unsigned int v = d_partial[(size_t)b * NWORDS + w];
        lo += v & 0xFFFFu;
        hi += v >> 16;
    }
    d_C[2 * w]     = (int)lo;
    d_C[2 * w + 1] = (int)hi;
}

__global__ void finalize_kernel(float* __restrict__ out) {
    __shared__ int   gt_size[LBL], pred_size[LBL];
    __shared__ int   best_p[LBL], inter_s[LBL], rowpairs_s[LBL], colcnt_s[LBL];
    __shared__ unsigned char has_s[LBL];
    int t = threadIdx.x;

    // Full row/col sums (background included, matching reference gt_size/pred_size)
    int rs = 0, cs = 0;
    #pragma unroll 8
    for (int j = 0; j < LBL; j++) {
        rs += d_C[t * LBL + j];
        cs += d_C[j * LBL + t];
    }
    gt_size[t]   = rs;
    pred_size[t] = cs;
    __syncthreads();

    // Per-row (gt label t>0) over Cnz (row 0 / col 0 zeroed => loop from 1):
    //   rowpairs: #overlapping preds; M: first p with 2*C > gt_size (argmax of bool)
    // Per-col (pred label t>0): count of overlapping gt rows (for ea).
    int rowpairs = 0, bp = 0, iv = 0, colcnt = 0;
    bool hv = false;
    if (t > 0) {
        int gs = gt_size[t];
        for (int p = 1; p < LBL; p++) {
            int c = d_C[t * LBL + p];
            rowpairs += (c > 0);
            if (!hv && 2 * c > gs) { hv = true; bp = p; iv = c; }
            colcnt += (d_C[p * LBL + t] > 0);
        }
    }
    rowpairs_s[t] = rowpairs;
    best_p[t]     = bp;
    inter_s[t]    = iv;
    has_s[t]      = hv ? 1 : 0;
    colcnt_s[t]   = colcnt;
    __syncthreads();

    if (t == 0) {
        int pairs = 0, ea = 0, num_gt = 0, num_pred = 0;
        for (int i = 1; i < LBL; i++) {
            pairs    += rowpairs_s[i];
            ea       += (colcnt_s[i] > 1);
            num_gt   += (gt_size[i]  > 0);
            num_pred += (pred_size[i] > 0);
        }
        bool used[LBL];
        for (int i = 0; i < LBL; i++) used[i] = false;
        int tp = 0;
        float seg_sum = 0.0f;
        // Greedy scan in ascending gt-label order (matches jax.lax.scan order)
        for (int g = 1; g < LBL; g++) {
            int pl = best_p[g];
            if (has_s[g] && !used[pl]) {
                int uni = gt_size[g] + pred_size[pl] - inter_s[g];
                if (uni < 1) uni = 1;
                seg_sum += (float)inter_s[g] / (float)uni;
                used[pl] = true;
                tp++;
            }
        }
        float ng = (float)(num_gt > 0 ? num_gt : 1);
        float seg = seg_sum / ng;
        int ns = pairs - tp;
        int fn = num_gt - tp;
        int fp = num_pred - tp;
        float det = 1.0f - (float)(fp + fn + ns + ea) / ng;
        bool both_empty = (num_gt == 0) && (num_pred == 0);
        bool any_empty  = (num_gt == 0) || (num_pred == 0);
        if (both_empty)     { seg = 1.0f; det = 1.0f; }
        else if (any_empty) { seg = 0.0f; det = 0.0f; }
        out[0] = seg;
        out[1] = det;
    }
}

extern "C" void kernel_launch(void* const* d_in, const int* in_sizes, int n_in,
                              void* d_out, int out_size) {
    const int* pred = (const int*)d_in[0];
    const int* gt   = (const int*)d_in[1];
    int n  = in_sizes[0];
    int n4 = n / 4;

    cudaFuncSetAttribute(hist_kernel,
                         cudaFuncAttributeMaxDynamicSharedMemorySize, SMEM_BYTES);

    hist_kernel<<<NB, THREADS, SMEM_BYTES>>>((const int4*)pred, (const int4*)gt,
                                             pred, gt, n4, n);
    reduce_kernel<<<NWORDS / 256, 256>>>();
    finalize_kernel<<<1, LBL>>>((float*)d_out);
}

// round 3
// speedup vs baseline: 2.9196x; 2.0197x over previous
#include <cuda_runtime.h>

#define LBL    256
#define NBINS  (LBL * LBL)       // 65536
#define NWORDS (NBINS / 2)       // 32768 u32 words, 2 packed u16 bins each
#define NB     296               // 2 waves of 148; <65536 pixels/block => u16 safe
#define THREADS 1024
#define SMEM_BYTES (NWORDS * 4)  // 131072

__device__ unsigned int d_partial[(size_t)NB * NWORDS]; // per-block u16-packed partials
__device__ int g_gt_size[LBL];
__device__ int g_pred_size[LBL];   // atomic target (zeroed in hist)
__device__ int g_colcnt[LBL];      // atomic target (zeroed in hist)
__device__ int g_rowpairs[LBL];
__device__ int g_best_p[LBL];
__device__ int g_inter[LBL];
__device__ int g_has[LBL];

__global__ void hist_kernel(const int4* __restrict__ p4,
                            const int4* __restrict__ g4,
                            const int*  __restrict__ p_s,
                            const int*  __restrict__ g_s,
                            int n4, int n) {
    extern __shared__ unsigned int sh[];   // 32768 words = 65536 u16 bins
    // zero the small atomic-target arrays for the later kernels (any block-0 thread,
    // visible because rowscan launches only after hist completes)
    if (blockIdx.x == 0 && threadIdx.x < LBL) {
        g_pred_size[threadIdx.x] = 0;
        g_colcnt[threadIdx.x]    = 0;
    }
    for (int w = threadIdx.x; w < NWORDS; w += THREADS) sh[w] = 0u;
    __syncthreads();

    int i = blockIdx.x * THREADS + threadIdx.x;
    int stride = gridDim.x * THREADS;
    for (; i < n4; i += stride) {
        int4 p = __ldg(&p4[i]);
        int4 g = __ldg(&g4[i]);
        int b;
        b = (g.x << 8) | p.x; atomicAdd(&sh[b >> 1], 1u << ((b & 1) << 4));
        b = (g.y << 8) | p.y; atomicAdd(&sh[b >> 1], 1u << ((b & 1) << 4));
        b = (g.z << 8) | p.z; atomicAdd(&sh[b >> 1], 1u << ((b & 1) << 4));
        b = (g.w << 8) | p.w; atomicAdd(&sh[b >> 1], 1u << ((b & 1) << 4));
    }
    // tail (n % 4) handled by block 0, folded into its smem histogram
    if (blockIdx.x == 0) {
        int base = n4 * 4;
        int rem = n - base;
        if ((int)threadIdx.x < rem) {
            int p = __ldg(&p_s[base + threadIdx.x]);
            int g = __ldg(&g_s[base + threadIdx.x]);
            int b = (g << 8) | p;
            atomicAdd(&sh[b >> 1], 1u << ((b & 1) << 4));
        }
    }
    __syncthreads();

    // Non-atomic flush: full 128KB partial, coalesced STG
    unsigned int* out = d_partial + (size_t)blockIdx.x * NWORDS;
    for (int w = threadIdx.x; w < NWORDS; w += THREADS) out[w] = sh[w];
}

// One block per gt row g; 128 threads, thread w owns packed word (g*128+w)
// i.e. bins p0=2w, p1=2w+1. Computes all per-row quantities in-block.
__global__ void rowscan_kernel() {
    int g = blockIdx.x;
    int w = threadIdx.x;                 // 0..127
    int lane = w & 31, wid = w >> 5;

    __shared__ int s_sum[4];
    __shared__ int s_pairs[4];
    __shared__ int s_gs;
    __shared__ int s_minp;
    if (w == 0) s_minp = 0x7fffffff;

    const unsigned int* src = d_partial + (size_t)g * 128 + w;
    unsigned int lo = 0, hi = 0;
    #pragma unroll 8
    for (int b = 0; b < NB; b++) {
        unsigned int v = src[(size_t)b * NWORDS];
        lo += v & 0xFFFFu;
        hi += v >> 16;
    }
    int p0 = 2 * w, p1 = 2 * w + 1;
    int c0 = (int)lo, c1 = (int)hi;

    // full column sums (all g, incl. background row) -> pred_size
    if (c0) atomicAdd(&g_pred_size[p0], c0);
    if (c1) atomicAdd(&g_pred_size[p1], c1);

    // full row sum (incl. p=0) -> gt_size[g]
    int rsum = c0 + c1;
    #pragma unroll
    for (int o = 16; o; o >>= 1) rsum += __shfl_down_sync(0xffffffffu, rsum, o);
    if (lane == 0) s_sum[wid] = rsum;
    __syncthreads();
    if (w == 0) {
        s_gs = s_sum[0] + s_sum[1] + s_sum[2] + s_sum[3];
        g_gt_size[g] = s_gs;
    }
    __syncthreads();
    int gs = s_gs;

    // Cnz: zero out row 0 / col 0
    int z0 = (g > 0 && p0 > 0) ? c0 : 0;
    int z1 = (g > 0)           ? c1 : 0;   // p1 >= 1 always

    if (g > 0) {
        if (z0) atomicAdd(&g_colcnt[p0], 1);
        if (z1) atomicAdd(&g_colcnt[p1], 1);
    }

    // rowpairs
    int pr = (z0 > 0) + (z1 > 0);
    #pragma unroll
    for (int o = 16; o; o >>= 1) pr += __shfl_down_sync(0xffffffffu, pr, o);
    if (lane == 0) s_pairs[wid] = pr;

    // majority match: first (lowest) p with 2*Cnz > gt_size
    if (2 * z0 > gs) atomicMin(&s_minp, p0);
    if (2 * z1 > gs) atomicMin(&s_minp, p1);
    __syncthreads();

    int minp = s_minp;
    if (w == 0) {
        g_rowpairs[g] = s_pairs[0] + s_pairs[1] + s_pairs[2] + s_pairs[3];
        bool hv = (minp != 0x7fffffff);
        g_has[g]    = hv ? 1 : 0;
        g_best_p[g] = hv ? minp : 0;      // argmax of all-false mask = 0
        if (!hv) g_inter[g] = 0;          // Cnz[g,0] = 0
    }
    if (minp == p0) g_inter[g] = z0;
    else if (minp == p1) g_inter[g] = z1;
}

__global__ void finalize_kernel(float* __restrict__ out) {
    __shared__ int   sh_gt[LBL], sh_ps[LBL], sh_bp[LBL], sh_in[LBL];
    __shared__ unsigned char sh_has[LBL];
    __shared__ int   s_red[4][8];
    int t = threadIdx.x;           // 256 threads
    int lane = t & 31, wid = t >> 5;

    int gt = g_gt_size[t];
    int ps = g_pred_size[t];
    sh_gt[t]  = gt;
    sh_ps[t]  = ps;
    sh_bp[t]  = g_best_p[t];
    sh_in[t]  = g_inter[t];
    sh_has[t] = (unsigned char)g_has[t];

    int v_pairs = (t > 0) ? g_rowpairs[t] : 0;
    int v_ea    = (t > 0 && g_colcnt[t] > 1) ? 1 : 0;
    int v_ng    = (t > 0 && gt > 0) ? 1 : 0;
    int v_np    = (t > 0 && ps > 0) ? 1 : 0;
    #pragma unroll
    for (int o = 16; o; o >>= 1) {
        v_pairs += __shfl_down_sync(0xffffffffu, v_pairs, o);
        v_ea    += __shfl_down_sync(0xffffffffu, v_ea, o);
        v_ng    += __shfl_down_sync(0xffffffffu, v_ng, o);
        v_np    += __shfl_down_sync(0xffffffffu, v_np, o);
    }
    if (lane == 0) {
        s_red[0][wid] = v_pairs;
        s_red[1][wid] = v_ea;
        s_red[2][wid] = v_ng;
        s_red[3][wid] = v_np;
    }
    __syncthreads();

    if (t == 0) {
        int pairs = 0, ea = 0, num_gt = 0, num_pred = 0;
        for (int i = 0; i < 8; i++) {
            pairs    += s_red[0][i];
            ea       += s_red[1][i];
            num_gt   += s_red[2][i];
            num_pred += s_red[3][i];
        }
        bool used[LBL];
        for (int i = 0; i < LBL; i++) used[i] = false;
        int tp = 0;
        float seg_sum = 0.0f;
        // Greedy scan in ascending gt-label order (matches jax.lax.scan order)
        for (int g = 1; g < LBL; g++) {
            int pl = sh_bp[g];
            if (sh_has[g] && !used[pl]) {
                int uni = sh_gt[g] + sh_ps[pl] - sh_in[g];
                if (uni < 1) uni = 1;
                seg_sum += (float)sh_in[g] / (float)uni;
                used[pl] = true;
                tp++;
            }
        }
        float ng = (float)(num_gt > 0 ? num_gt : 1);
        float seg = seg_sum / ng;
        int ns = pairs - tp;
        int fn = num_gt - tp;
        int fp = num_pred - tp;
        float det = 1.0f - (float)(fp + fn + ns + ea) / ng;
        bool both_empty = (num_gt == 0) && (num_pred == 0);
        bool any_empty  = (num_gt == 0) || (num_pred == 0);
        if (both_empty)     { seg = 1.0f; det = 1.0f; }
        else if (any_empty) { seg = 0.0f; det = 0.0f; }
        out[0] = seg;
        out[1] = det;
    }
}

extern "C" void kernel_launch(void* const* d_in, const int* in_sizes, int n_in,
                              void* d_out, int out_size) {
    const int* pred = (const int*)d_in[0];
    const int* gt   = (const int*)d_in[1];
    int n  = in_sizes[0];
    int n4 = n / 4;

    cudaFuncSetAttribute(hist_kernel,
                         cudaFuncAttributeMaxDynamicSharedMemorySize, SMEM_BYTES);

    hist_kernel<<<NB, THREADS, SMEM_BYTES>>>((const int4*)pred, (const int4*)gt,
                                             pred, gt, n4, n);
    rowscan_kernel<<<LBL, 128>>>();
    finalize_kernel<<<1, LBL>>>((float*)d_out);
}

// round 4
// speedup vs baseline: 3.6964x; 1.2661x over previous
#include <cuda_runtime.h>

#define LBL    256
#define NBINS  (LBL * LBL)       // 65536
#define NWORDS (NBINS / 2)       // 32768 u32 words, 2 packed u16 bins each
#define NB     296               // 2 waves of 148; <65536 pixels/block => u16 safe
#define THREADS 1024
#define SMEM_BYTES (NWORDS * 4)  // 131072

__device__ unsigned int d_partial[(size_t)NB * NWORDS]; // per-block u16-packed partials
__device__ int g_gt_size[LBL];
__device__ int g_pred_size[LBL];   // atomic target (zeroed in hist)
__device__ int g_colcnt[LBL];      // atomic target (zeroed in hist)
__device__ int g_rowpairs[LBL];
__device__ int g_best_p[LBL];
__device__ int g_inter[LBL];
__device__ int g_has[LBL];

__global__ void hist_kernel(const int4* __restrict__ p4,
                            const int4* __restrict__ g4,
                            const int*  __restrict__ p_s,
                            const int*  __restrict__ g_s,
                            int n4, int n) {
    extern __shared__ unsigned int sh[];   // 32768 words = 65536 u16 bins
    if (blockIdx.x == 0 && threadIdx.x < LBL) {
        g_pred_size[threadIdx.x] = 0;
        g_colcnt[threadIdx.x]    = 0;
    }
    for (int w = threadIdx.x; w < NWORDS; w += THREADS) sh[w] = 0u;
    __syncthreads();

    int i = blockIdx.x * THREADS + threadIdx.x;
    int stride = gridDim.x * THREADS;
    // unroll-2: batch 2x int4 loads per side up-front for higher MLP
    for (; i + stride < n4; i += 2 * stride) {
        int4 pa = __ldg(&p4[i]);
        int4 ga = __ldg(&g4[i]);
        int4 pb = __ldg(&p4[i + stride]);
        int4 gb = __ldg(&g4[i + stride]);
        int b;
        b = (ga.x << 8) | pa.x; atomicAdd(&sh[b >> 1], 1u << ((b & 1) << 4));
        b = (ga.y << 8) | pa.y; atomicAdd(&sh[b >> 1], 1u << ((b & 1) << 4));
        b = (ga.z << 8) | pa.z; atomicAdd(&sh[b >> 1], 1u << ((b & 1) << 4));
        b = (ga.w << 8) | pa.w; atomicAdd(&sh[b >> 1], 1u << ((b & 1) << 4));
        b = (gb.x << 8) | pb.x; atomicAdd(&sh[b >> 1], 1u << ((b & 1) << 4));
        b = (gb.y << 8) | pb.y; atomicAdd(&sh[b >> 1], 1u << ((b & 1) << 4));
        b = (gb.z << 8) | pb.z; atomicAdd(&sh[b >> 1], 1u << ((b & 1) << 4));
        b = (gb.w << 8) | pb.w; atomicAdd(&sh[b >> 1], 1u << ((b & 1) << 4));
    }
    if (i < n4) {
        int4 p = __ldg(&p4[i]);
        int4 g = __ldg(&g4[i]);
        int b;
        b = (g.x << 8) | p.x; atomicAdd(&sh[b >> 1], 1u << ((b & 1) << 4));
        b = (g.y << 8) | p.y; atomicAdd(&sh[b >> 1], 1u << ((b & 1) << 4));
        b = (g.z << 8) | p.z; atomicAdd(&sh[b >> 1], 1u << ((b & 1) << 4));
        b = (g.w << 8) | p.w; atomicAdd(&sh[b >> 1], 1u << ((b & 1) << 4));
    }
    // tail (n % 4) handled by block 0, folded into its smem histogram
    if (blockIdx.x == 0) {
        int base = n4 * 4;
        int rem = n - base;
        if ((int)threadIdx.x < rem) {
            int p = __ldg(&p_s[base + threadIdx.x]);
            int g = __ldg(&g_s[base + threadIdx.x]);
            int b = (g << 8) | p;
            atomicAdd(&sh[b >> 1], 1u << ((b & 1) << 4));
        }
    }
    __syncthreads();

    // Non-atomic flush: full 128KB partial, coalesced STG
    unsigned int* out = d_partial + (size_t)blockIdx.x * NWORDS;
    for (int w = threadIdx.x; w < NWORDS; w += THREADS) out[w] = sh[w];
}

// One block per gt row g; 1024 threads = 8 sub-threads per packed word.
// Sub s sums partials b = s, s+8, ... (37 each), then smem-reduce across s.
__global__ void rowscan_kernel() {
    int g = blockIdx.x;
    int t = threadIdx.x;                 // 0..1023
    int w = t & 127;                     // packed word within row
    int s = t >> 7;                      // sub-slice 0..7

    __shared__ unsigned int sh_lo[8][128];
    __shared__ unsigned int sh_hi[8][128];
    __shared__ int s_sum[4];
    __shared__ int s_pairs[4];
    __shared__ int s_gs;
    __shared__ int s_minp;
    if (t == 0) s_minp = 0x7fffffff;

    const unsigned int* src = d_partial + (size_t)g * 128 + w;
    unsigned int lo = 0, hi = 0;
    #pragma unroll 8
    for (int b = s; b < NB; b += 8) {
        unsigned int v = src[(size_t)b * NWORDS];
        lo += v & 0xFFFFu;
        hi += v >> 16;
    }
    sh_lo[s][w] = lo;
    sh_hi[s][w] = hi;
    __syncthreads();

    if (t < 128) {                        // now w == t, s == 0
        int lane = t & 31, wid = t >> 5;
        unsigned int L = 0, H = 0;
        #pragma unroll
        for (int k = 0; k < 8; k++) { L += sh_lo[k][t]; H += sh_hi[k][t]; }
        int p0 = 2 * t, p1 = 2 * t + 1;
        int c0 = (int)L, c1 = (int)H;

        // full column sums (all g, incl. background row) -> pred_size
        if (c0) atomicAdd(&g_pred_size[p0], c0);
        if (c1) atomicAdd(&g_pred_size[p1], c1);

        // full row sum (incl. p=0) -> gt_size[g]
        int rsum = c0 + c1;
        #pragma unroll
        for (int o = 16; o; o >>= 1) rsum += __shfl_down_sync(0xffffffffu, rsum, o);
        if (lane == 0) s_sum[wid] = rsum;
        __syncwarp();
        if (t == 0) {
            s_gs = s_sum[0] + s_sum[1] + s_sum[2] + s_sum[3];
            g_gt_size[g] = s_gs;
        }
        __syncwarp();
    }
    __syncthreads();
    if (t < 128) {
        int lane = t & 31, wid = t >> 5;
        unsigned int L = 0, H = 0;
        #pragma unroll
        for (int k = 0; k < 8; k++) { L += sh_lo[k][t]; H += sh_hi[k][t]; }
        int p0 = 2 * t, p1 = 2 * t + 1;
        int c0 = (int)L, c1 = (int)H;
        int gs = s_gs;

        // Cnz: zero out row 0 / col 0
        int z0 = (g > 0 && p0 > 0) ? c0 : 0;
        int z1 = (g > 0)           ? c1 : 0;     // p1 >= 1 always

        if (g > 0) {
            if (z0) atomicAdd(&g_colcnt[p0], 1);
            if (z1) atomicAdd(&g_colcnt[p1], 1);
        }

        // rowpairs
        int pr = (z0 > 0) + (z1 > 0);
        #pragma unroll
        for (int o = 16; o; o >>= 1) pr += __shfl_down_sync(0xffffffffu, pr, o);
        if (lane == 0) s_pairs[wid] = pr;

        // majority match: first (lowest) p with 2*Cnz > gt_size
        if (2 * z0 > gs) atomicMin(&s_minp, p0);
        if (2 * z1 > gs) atomicMin(&s_minp, p1);
        __syncthreads();

        int minp = s_minp;
        if (t == 0) {
            g_rowpairs[g] = s_pairs[0] + s_pairs[1] + s_pairs[2] + s_pairs[3];
            bool hv = (minp != 0x7fffffff);
            g_has[g]    = hv ? 1 : 0;
            g_best_p[g] = hv ? minp : 0;      // argmax of all-false mask = 0
            if (!hv) g_inter[g] = 0;          // Cnz[g,0] = 0
        }
        if (minp == p0) g_inter[g] = z0;
        else if (minp == p1) g_inter[g] = z1;
    } else {
        __syncthreads();                       // match barrier in t<128 branch
    }
}

__global__ void finalize_kernel(float* __restrict__ out) {
    __shared__ int   sh_gt[LBL], sh_ps[LBL], sh_bp[LBL], sh_in[LBL];
    __shared__ unsigned char sh_has[LBL];
    __shared__ int   s_red[4][8];
    int t = threadIdx.x;           // 256 threads
    int lane = t & 31, wid = t >> 5;

    int gt = g_gt_size[t];
    int ps = g_pred_size[t];
    sh_gt[t]  = gt;
    sh_ps[t]  = ps;
    sh_bp[t]  = g_best_p[t];
    sh_in[t]  = g_inter[t];
    sh_has[t] = (unsigned char)g_has[t];

    int v_pairs = (t > 0) ? g_rowpairs[t] : 0;
    int v_ea    = (t > 0 && g_colcnt[t] > 1) ? 1 : 0;
    int v_ng    = (t > 0 && gt > 0) ? 1 : 0;
    int v_np    = (t > 0 && ps > 0) ? 1 : 0;
    #pragma unroll
    for (int o = 16; o; o >>= 1) {
        v_pairs += __shfl_down_sync(0xffffffffu, v_pairs, o);
        v_ea    += __shfl_down_sync(0xffffffffu, v_ea, o);
        v_ng    += __shfl_down_sync(0xffffffffu, v_ng, o);
        v_np    += __shfl_down_sync(0xffffffffu, v_np, o);
    }
    if (lane == 0) {
        s_red[0][wid] = v_pairs;
        s_red[1][wid] = v_ea;
        s_red[2][wid] = v_ng;
        s_red[3][wid] = v_np;
    }
    __syncthreads();

    if (t == 0) {
        int pairs = 0, ea = 0, num_gt = 0, num_pred = 0;
        for (int i = 0; i < 8; i++) {
            pairs    += s_red[0][i];
            ea       += s_red[1][i];
            num_gt   += s_red[2][i];
            num_pred += s_red[3][i];
        }
        bool used[LBL];
        for (int i = 0; i < LBL; i++) used[i] = false;
        int tp = 0;
        float seg_sum = 0.0f;
        // Greedy scan in ascending gt-label order (matches jax.lax.scan order)
        for (int g = 1; g < LBL; g++) {
            int pl = sh_bp[g];
            if (sh_has[g] && !used[pl]) {
                int uni = sh_gt[g] + sh_ps[pl] - sh_in[g];
                if (uni < 1) uni = 1;
                seg_sum += (float)sh_in[g] / (float)uni;
                used[pl] = true;
                tp++;
            }
        }
        float ng = (float)(num_gt > 0 ? num_gt : 1);
        float seg = seg_sum / ng;
        int ns = pairs - tp;
        int fn = num_gt - tp;
        int fp = num_pred - tp;
        float det = 1.0f - (float)(fp + fn + ns + ea) / ng;
        bool both_empty = (num_gt == 0) && (num_pred == 0);
        bool any_empty  = (num_gt == 0) || (num_pred == 0);
        if (both_empty)     { seg = 1.0f; det = 1.0f; }
        else if (any_empty) { seg = 0.0f; det = 0.0f; }
        out[0] = seg;
        out[1] = det;
    }
}

extern "C" void kernel_launch(void* const* d_in, const int* in_sizes, int n_in,
                              void* d_out, int out_size) {
    const int* pred = (const int*)d_in[0];
    const int* gt   = (const int*)d_in[1];
    int n  = in_sizes[0];
    int n4 = n / 4;

    cudaFuncSetAttribute(hist_kernel,
                         cudaFuncAttributeMaxDynamicSharedMemorySize, SMEM_BYTES);

    hist_kernel<<<NB, THREADS, SMEM_BYTES>>>((const int4*)pred, (const int4*)gt,
                                             pred, gt, n4, n);
    rowscan_kernel<<<LBL, 1024>>>();
    finalize_kernel<<<1, LBL>>>((float*)d_out);
}